// round 15
// baseline (speedup 1.0000x reference)
#include <cuda_runtime.h>
#include <cstdint>

// dynFilter: out[b,1,h,w] = tanh( sum_{c,ky,kx} x[b,c,h+ky-2,w+kx-2] * filt[b, c*25+ky*5+kx, h, w] )
// x [8,4,256,256] f32, filt [8,100,256,256] f32, out [8,1,256,256] f32.
// LDG path exhausted at 37.4us / DRAM 73% (reg-bounded per-warp MLP).
// R15: cp.async.bulk (UBLKCP) producer/consumer pipeline. Full-width tile
// (TILE_H=2) makes each filt plane slice ONE contiguous 2048B bulk copy.
// Ring of 2 stages x (5 planes = 10KB), mbarrier full/empty, producer = tid 0.
// In-flight bytes now set by the async engine, not the register file.
// 512 CTAs x 2 tiles each = 1024 tiles, 4 CTAs/SM, single balanced wave.

#define KK 5
#define PADK 2
#define CC 4
#define HH 256
#define WW 256
#define TILE_H 2
#define NROWS (TILE_H + 2 * PADK)     // 6 halo rows
#define NCOLS (WW + 2 * PADK)         // 260 used cols
#define NCOLS_PAD 264
#define DQ 2                          // ring stages
#define NGT (CC * KK)                 // 20 groups per tile (one per (c,ky))
#define PLANE_BYTES (TILE_H * WW * 4) // 2048
#define STAGE_BYTES (KK * PLANE_BYTES)// 10240

__device__ __forceinline__ float tanh_approx(float v) {
    float r;
    asm("tanh.approx.f32 %0, %1;" : "=f"(r) : "f"(v));
    return r;
}
__device__ __forceinline__ uint32_t smem_u32(const void* p) {
    return (uint32_t)__cvta_generic_to_shared(p);
}
__device__ __forceinline__ void mbar_init(uint32_t a, uint32_t cnt) {
    asm volatile("mbarrier.init.shared.b64 [%0], %1;" :: "r"(a), "r"(cnt) : "memory");
}
__device__ __forceinline__ void mbar_expect_tx(uint32_t a, uint32_t bytes) {
    asm volatile("mbarrier.arrive.expect_tx.shared.b64 _, [%0], %1;" :: "r"(a), "r"(bytes) : "memory");
}
__device__ __forceinline__ void mbar_arrive(uint32_t a) {
    asm volatile("mbarrier.arrive.shared.b64 _, [%0];" :: "r"(a) : "memory");
}
__device__ __forceinline__ void mbar_wait(uint32_t a, uint32_t parity) {
    uint32_t done;
    asm volatile(
        "{\n\t.reg .pred p;\n\t"
        "mbarrier.try_wait.parity.acquire.cta.shared::cta.b64 p, [%1], %2;\n\t"
        "selp.b32 %0, 1, 0, p;\n\t}"
        : "=r"(done) : "r"(a), "r"(parity) : "memory");
    if (!done) {
        asm volatile(
            "{\n\t.reg .pred P1;\n\t"
            "W_%=:\n\t"
            "mbarrier.try_wait.parity.acquire.cta.shared::cta.b64 P1, [%0], %1, 0x989680;\n\t"
            "@P1 bra.uni D_%=;\n\t"
            "bra.uni W_%=;\n\t"
            "D_%=:\n\t}"
            :: "r"(a), "r"(parity) : "memory");
    }
}
__device__ __forceinline__ void bulk_g2s(uint32_t dst, const void* src,
                                         uint32_t bytes, uint32_t mbar) {
    asm volatile(
        "cp.async.bulk.shared::cluster.global.mbarrier::complete_tx::bytes "
        "[%0], [%1], %2, [%3];"
        :: "r"(dst), "l"(src), "r"(bytes), "r"(mbar) : "memory");
}

__global__ __launch_bounds__(128, 4)
void dynfilter_kernel(const float* __restrict__ x,
                      const float* __restrict__ filt,
                      float* __restrict__ out)
{
    __shared__ __align__(16) float xs[CC][NROWS][NCOLS_PAD];      // 25344 B
    __shared__ __align__(16) float ring[DQ][KK][TILE_H * WW];     // 20480 B
    __shared__ __align__(8)  uint64_t mbf[DQ];
    __shared__ __align__(8)  uint64_t mbe[DQ];

    const int tid = threadIdx.x;
    const int t0  = blockIdx.x * 2;           // first of 2 tiles

    const uint32_t ringb = smem_u32(&ring[0][0][0]);
    const uint32_t fullb = smem_u32(&mbf[0]);
    const uint32_t empb  = smem_u32(&mbe[0]);

    if (tid == 0) {
        #pragma unroll
        for (int s = 0; s < DQ; ++s) {
            mbar_init(fullb + 8u * s, 1);
            mbar_init(empb  + 8u * s, 128);
        }
        asm volatile("fence.proxy.async.shared::cta;" ::: "memory");
    }
    __syncthreads();

    // Producer: issue absolute group g (0..2*NGT-1) into slot g%DQ.
    auto issue_group = [&](int g) {
        const int tile = t0 + g / NGT;
        const int gl   = g % NGT;                 // (c,ky) index
        const int b    = tile >> 7;
        const int h0   = (tile & 127) * TILE_H;
        const float* fb = filt + (((long)b * (CC * KK * KK)) * HH + h0) * WW;
        const int slot = g % DQ;
        mbar_expect_tx(fullb + 8u * slot, STAGE_BYTES);
        #pragma unroll
        for (int kx = 0; kx < KK; ++kx) {
            const uint32_t dst = ringb + (uint32_t)(slot * KK + kx) * PLANE_BYTES;
            const float* src = fb + (long)(gl * KK + kx) * (HH * WW);
            bulk_g2s(dst, src, PLANE_BYTES, fullb + 8u * slot);
        }
    };

    // Prime pipeline (tile t0 groups 0..DQ-1) before the xs fill.
    if (tid == 0) {
        #pragma unroll
        for (int g = 0; g < DQ; ++g) issue_group(g);
    }

    const int hr = tid >> 6;        // 0..1 output row within tile
    const int q  = tid & 63;        // 0..63 float4 column
    const int w  = q << 2;

    #pragma unroll 1
    for (int tt = 0; tt < 2; ++tt) {
        const int tile = t0 + tt;
        const int b    = tile >> 7;
        const int h0   = (tile & 127) * TILE_H;

        // Fill xs for this tile (all threads). For tt=1, ensure tile0 windows done.
        if (tt) __syncthreads();
        for (int idx = tid; idx < CC * NROWS * NCOLS; idx += 128) {
            const int c   = idx / (NROWS * NCOLS);
            const int rem = idx % (NROWS * NCOLS);
            const int r   = rem / NCOLS;
            const int cx  = rem % NCOLS;
            const int gr  = h0 - PADK + r;
            const int gc  = cx - PADK;
            float v = 0.0f;
            if (gr >= 0 && gr < HH && gc >= 0 && gc < WW)
                v = __ldg(&x[(((b * CC) + c) * HH + gr) * WW + gc]);
            xs[c][r][cx] = v;
        }
        __syncthreads();

        float acc0 = 0.f, acc1 = 0.f, acc2 = 0.f, acc3 = 0.f;

        #pragma unroll
        for (int gl = 0; gl < NGT; ++gl) {
            const int g    = tt * NGT + gl;
            const int slot = g % DQ;
            const uint32_t phase = (uint32_t)((g / DQ) & 1);
            const int c  = gl / KK;
            const int ky = gl % KK;

            // Wait stage data (acquire).
            mbar_wait(fullb + 8u * slot, phase);

            // 8-float window row (conflict-free LDS.128).
            const float4 a  = *(const float4*)&xs[c][hr + ky][w];
            const float4 bb = *(const float4*)&xs[c][hr + ky][w + 4];
            const float x0 = a.x,  x1 = a.y,  x2 = a.z,  x3 = a.w;
            const float x4 = bb.x, x5 = bb.y, x6 = bb.z, x7 = bb.w;

            // 5 ring reads (this thread's float4 per plane) + 20 FMAs.
            #pragma unroll
            for (int kx = 0; kx < KK; ++kx) {
                const float4 f = *(const float4*)&ring[slot][kx][hr * WW + w];
                const float wv0 = (kx == 0) ? x0 : (kx == 1) ? x1 : (kx == 2) ? x2 : (kx == 3) ? x3 : x4;
                const float wv1 = (kx == 0) ? x1 : (kx == 1) ? x2 : (kx == 2) ? x3 : (kx == 3) ? x4 : x5;
                const float wv2 = (kx == 0) ? x2 : (kx == 1) ? x3 : (kx == 2) ? x4 : (kx == 3) ? x5 : x6;
                const float wv3 = (kx == 0) ? x3 : (kx == 1) ? x4 : (kx == 2) ? x5 : (kx == 3) ? x6 : x7;
                acc0 = fmaf(wv0, f.x, acc0);
                acc1 = fmaf(wv1, f.y, acc1);
                acc2 = fmaf(wv2, f.z, acc2);
                acc3 = fmaf(wv3, f.w, acc3);
            }

            // Release slot; producer refills with group g+DQ.
            mbar_arrive(empb + 8u * slot);
            if (tid == 0 && (g + DQ) < 2 * NGT) {
                mbar_wait(empb + 8u * slot, phase);   // all 128 arrived
                issue_group(g + DQ);
            }
        }

        float4 o;
        o.x = tanh_approx(acc0);
        o.y = tanh_approx(acc1);
        o.z = tanh_approx(acc2);
        o.w = tanh_approx(acc3);
        ((float4*)out)[((long)b * HH + (h0 + hr)) * (WW / 4) + q] = o;
    }
}

extern "C" void kernel_launch(void* const* d_in, const int* in_sizes, int n_in,
                              void* d_out, int out_size)
{
    const float* x    = (const float*)d_in[0];   // [8,4,256,256]
    const float* filt = (const float*)d_in[1];   // [8,100,256,256]
    float* out        = (float*)d_out;           // [8,1,256,256]

    dim3 grid(512);      // 512 workers x 2 tiles = 1024 tiles
    dim3 block(128);
    dynfilter_kernel<<<grid, block>>>(x, filt, out);
}